// round 5
// baseline (speedup 1.0000x reference)
#include <cuda_runtime.h>
#include <cuda_fp16.h>

// Problem shapes are fixed by the dataset.
#define NPOI   50000
#define NNODES 100000
#define NEDGES 1000000
#define NDIST  512
#define DD     64
#define SLOTS  80   // per-node incidence bucket; degree ~ Poisson(20), P(>80) ~ 0

// Scratch (__device__ globals; no dynamic allocation allowed).
__device__ uint2 g_xh[NNODES * 16];     // node features, fp16 (12.8MB)
__device__ float g_ea[NNODES];          // exp(x[n] . w_src)
__device__ float g_ed[NNODES];          // exp(x[n] . w_dst)
__device__ int   g_cnt[NNODES];         // per-node incidence cursors
__device__ float g_w[2 * DD];           // w_src | w_dst
__device__ float g_expb[NDIST];         // exp(delta_dis_embs[k] . w_src)
__device__ int2  g_adj[NNODES * SLOTS]; // {neighbor, bits(f32 exp_weight)} (64MB)

// ---------------------------------------------------------------------------
// K0: w_src = alpha_src @ W, w_dst = alpha_dst @ W, expb[k] = exp(dis[k].w_src)
// ---------------------------------------------------------------------------
__global__ void k0_precompute(const float* __restrict__ W,
                              const float* __restrict__ asw,
                              const float* __restrict__ adw,
                              const float* __restrict__ dis) {
    __shared__ float ws[DD];
    int t = threadIdx.x;
    if (t < DD) {
        float s1 = 0.f, s2 = 0.f;
        #pragma unroll 8
        for (int f = 0; f < DD; f++) {
            float w = W[f * DD + t];
            s1 += asw[f] * w;
            s2 += adw[f] * w;
        }
        ws[t] = s1;
        g_w[t] = s1;
        g_w[DD + t] = s2;
    }
    __syncthreads();
    for (int k = t; k < NDIST; k += blockDim.x) {
        const float* row = dis + k * DD;
        float s = 0.f;
        #pragma unroll 8
        for (int d = 0; d < DD; d++) s += row[d] * ws[d];
        g_expb[k] = __expf(s);
    }
}

// ---------------------------------------------------------------------------
// K1: per node n: gather POI row, store fp16; exp of the two score dots;
// zero cursor. 16 threads per node, one float4 column chunk per lane.
// ---------------------------------------------------------------------------
__global__ void k1_nodes(const float* __restrict__ poi,
                         const int* __restrict__ sess) {
    int gt = blockIdx.x * blockDim.x + threadIdx.x;
    int n = gt >> 4;
    int c = gt & 15;
    if (n >= NNODES) return;

    int p = sess[n];
    float4 v = ((const float4*)poi)[(size_t)p * 16 + c];

    __half2 h0 = __floats2half2_rn(v.x, v.y);
    __half2 h1 = __floats2half2_rn(v.z, v.w);
    g_xh[(size_t)n * 16 + c] = make_uint2(*(const unsigned*)&h0, *(const unsigned*)&h1);

    const float4* w4 = (const float4*)g_w;
    float4 a = w4[c];
    float4 d = w4[16 + c];
    float rs = v.x * a.x + v.y * a.y + v.z * a.z + v.w * a.w;
    float rd = v.x * d.x + v.y * d.y + v.z * d.z + v.w * d.w;
    #pragma unroll
    for (int o = 8; o >= 1; o >>= 1) {
        rs += __shfl_down_sync(0xffffffffu, rs, o, 16);
        rd += __shfl_down_sync(0xffffffffu, rd, o, 16);
    }
    if (c == 0) {
        g_ea[n]  = __expf(rs);
        g_ed[n]  = __expf(rd);
        g_cnt[n] = 0;
    }
}

// ---------------------------------------------------------------------------
// K2: two edges per thread; append {neighbor, f32 weight} records for both
// directions. Weight = product of pre-exponentiated factors (one FMUL after
// the gather; no MUFU in the chain). No float atomics — K3 rebuilds the
// softmax denominator from the record weights. Max-subtraction omitted
// (scores ~ N(0,2), softmax is shift-invariant; f32 exp is safe).
// ---------------------------------------------------------------------------
__global__ void k2_build(const int* __restrict__ esrc,
                         const int* __restrict__ edst,
                         const int* __restrict__ edist) {
    int i = blockIdx.x * blockDim.x + threadIdx.x;
    if (i >= NEDGES / 2) return;
    int2 ss = __ldg(&((const int2*)esrc)[i]);
    int2 tt = __ldg(&((const int2*)edst)[i]);
    int2 kk = __ldg(&((const int2*)edist)[i]);

    float ef0 = __ldg(&g_ea[tt.x]) * __ldg(&g_expb[kk.x]);
    float ef1 = __ldg(&g_ea[tt.y]) * __ldg(&g_expb[kk.y]);
    float eb0 = __ldg(&g_ed[ss.x]);
    float eb1 = __ldg(&g_ed[ss.y]);

    int p0 = atomicAdd(&g_cnt[tt.x], 1);
    int p1 = atomicAdd(&g_cnt[ss.x], 1);
    int p2 = atomicAdd(&g_cnt[tt.y], 1);
    int p3 = atomicAdd(&g_cnt[ss.y], 1);
    if (p0 < SLOTS) g_adj[tt.x * SLOTS + p0] = make_int2(ss.x, __float_as_int(ef0));
    if (p1 < SLOTS) g_adj[ss.x * SLOTS + p1] = make_int2(tt.x, __float_as_int(eb0));
    if (p2 < SLOTS) g_adj[tt.y * SLOTS + p2] = make_int2(ss.y, __float_as_int(ef1));
    if (p3 < SLOTS) g_adj[ss.y * SLOTS + p3] = make_int2(tt.y, __float_as_int(eb1));
}

// ---------------------------------------------------------------------------
// K3: warp-per-node aggregation. Two half-warps; each half-warp batches FOUR
// records per iteration -> 8 independent L2 gathers in flight per warp.
// fp16 feature gathers (half the bytes of f32), f32 weights and accumulation;
// denominator summed from record weights; one coalesced normalized store.
// ---------------------------------------------------------------------------
__device__ __forceinline__ void fma4h(float4& acc, float wt, uint2 pk) {
    float2 f0 = __half22float2(*(const __half2*)&pk.x);
    float2 f1 = __half22float2(*(const __half2*)&pk.y);
    acc.x += wt * f0.x;
    acc.y += wt * f0.y;
    acc.z += wt * f1.x;
    acc.w += wt * f1.y;
}

__global__ void k3_agg(float* __restrict__ out) {
    int w = (blockIdx.x * blockDim.x + threadIdx.x) >> 5;
    if (w >= NNODES) return;
    int lane = threadIdx.x & 31;
    int c = lane & 15;
    int h = lane >> 4;

    int deg = g_cnt[w];
    if (deg > SLOTS) deg = SLOTS;
    const int2* adj = g_adj + (size_t)w * SLOTS;

    float4 acc = make_float4(0.f, 0.f, 0.f, 0.f);
    float  ssum = 0.f;

    int i = h;
    for (; i + 6 < deg; i += 8) {
        int2 r0 = __ldg(&adj[i]);
        int2 r1 = __ldg(&adj[i + 2]);
        int2 r2 = __ldg(&adj[i + 4]);
        int2 r3 = __ldg(&adj[i + 6]);
        uint2 v0 = __ldg(&g_xh[(size_t)r0.x * 16 + c]);
        uint2 v1 = __ldg(&g_xh[(size_t)r1.x * 16 + c]);
        uint2 v2 = __ldg(&g_xh[(size_t)r2.x * 16 + c]);
        uint2 v3 = __ldg(&g_xh[(size_t)r3.x * 16 + c]);
        float w0 = __int_as_float(r0.y);
        float w1 = __int_as_float(r1.y);
        float w2 = __int_as_float(r2.y);
        float w3 = __int_as_float(r3.y);
        ssum += (w0 + w1) + (w2 + w3);
        fma4h(acc, w0, v0);
        fma4h(acc, w1, v1);
        fma4h(acc, w2, v2);
        fma4h(acc, w3, v3);
    }
    for (; i < deg; i += 2) {
        int2 r = __ldg(&adj[i]);
        uint2 v = __ldg(&g_xh[(size_t)r.x * 16 + c]);
        float wt = __int_as_float(r.y);
        ssum += wt;
        fma4h(acc, wt, v);
    }

    // combine the two half-warp partials (columns align: lane c and lane c+16)
    acc.x += __shfl_down_sync(0xffffffffu, acc.x, 16);
    acc.y += __shfl_down_sync(0xffffffffu, acc.y, 16);
    acc.z += __shfl_down_sync(0xffffffffu, acc.z, 16);
    acc.w += __shfl_down_sync(0xffffffffu, acc.w, 16);
    ssum  += __shfl_down_sync(0xffffffffu, ssum, 16);

    if (h == 0) {
        float inv = 1.f / (ssum + 1e-16f);
        acc.x *= inv; acc.y *= inv; acc.z *= inv; acc.w *= inv;
        ((float4*)out)[(size_t)w * 16 + c] = acc;
    }
}

// ---------------------------------------------------------------------------
extern "C" void kernel_launch(void* const* d_in, const int* in_sizes, int n_in,
                              void* d_out, int out_size) {
    const float* poi   = (const float*)d_in[0];  // [NPOI, D]
    const float* dis   = (const float*)d_in[1];  // [NDIST, D]
    const float* W     = (const float*)d_in[2];  // [D, D]
    const float* asw   = (const float*)d_in[3];  // [D]
    const float* adw   = (const float*)d_in[4];  // [D]
    const int*   sess  = (const int*)d_in[5];    // [NNODES]
    const int*   ei    = (const int*)d_in[6];    // [2, NEDGES]
    const int*   edist = (const int*)d_in[7];    // [NEDGES]
    float* out = (float*)d_out;                  // [NNODES, D]

    const int* esrc = ei;
    const int* edst = ei + NEDGES;

    k0_precompute<<<1, 256>>>(W, asw, adw, dis);
    k1_nodes<<<(NNODES * 16 + 255) / 256, 256>>>(poi, sess);
    k2_build<<<(NEDGES / 2 + 255) / 256, 256>>>(esrc, edst, edist);
    k3_agg<<<(NNODES * 32 + 255) / 256, 256>>>(out);
}

// round 6
// speedup vs baseline: 1.0627x; 1.0627x over previous
#include <cuda_runtime.h>
#include <cuda_bf16.h>

// Problem shapes are fixed by the dataset.
#define NPOI   50000
#define NNODES 100000
#define NEDGES 1000000
#define NDIST  512
#define DD     64
#define SLOTS  80   // per-node incidence bucket; degree ~ Poisson(20), P(>80) ~ 0

// Scratch (__device__ globals; no dynamic allocation allowed).
// NOTE: no materialized node-feature array — x[n] == poi[sess[n]] exactly, so
// records carry the POI row id and K3 gathers from the (L2-resident, 12.8MB)
// poi input directly.
__device__ float g_ea[NNODES];          // exp(x[n] . w_src)
__device__ float g_ed[NNODES];          // exp(x[n] . w_dst)
__device__ int   g_cnt[NNODES];         // per-node incidence cursors
__device__ float g_w[2 * DD];           // w_src | w_dst
__device__ float g_expb[NDIST];         // exp(delta_dis_embs[k] . w_src)
__device__ int2  g_adj[NNODES * SLOTS]; // {poi_row(neighbor), bits(f32 weight)}

// ---------------------------------------------------------------------------
// K0: w_src = alpha_src @ W, w_dst = alpha_dst @ W, expb[k] = exp(dis[k].w_src)
// ---------------------------------------------------------------------------
__global__ void k0_precompute(const float* __restrict__ W,
                              const float* __restrict__ asw,
                              const float* __restrict__ adw,
                              const float* __restrict__ dis) {
    __shared__ float ws[DD];
    int t = threadIdx.x;
    if (t < DD) {
        float s1 = 0.f, s2 = 0.f;
        #pragma unroll 8
        for (int f = 0; f < DD; f++) {
            float w = W[f * DD + t];
            s1 += asw[f] * w;
            s2 += adw[f] * w;
        }
        ws[t] = s1;
        g_w[t] = s1;
        g_w[DD + t] = s2;
    }
    __syncthreads();
    for (int k = t; k < NDIST; k += blockDim.x) {
        const float* row = dis + k * DD;
        float s = 0.f;
        #pragma unroll 8
        for (int d = 0; d < DD; d++) s += row[d] * ws[d];
        g_expb[k] = __expf(s);
    }
}

// ---------------------------------------------------------------------------
// K1: per node n: exp of the two score dots vs POI[sess[n]]; zero cursor.
// 16 threads per node, one float4 column chunk per lane. No feature store.
// ---------------------------------------------------------------------------
__global__ void k1_nodes(const float* __restrict__ poi,
                         const int* __restrict__ sess) {
    int gt = blockIdx.x * blockDim.x + threadIdx.x;
    int n = gt >> 4;
    int c = gt & 15;
    if (n >= NNODES) return;

    int p = __ldg(&sess[n]);
    float4 v = __ldg(&((const float4*)poi)[(size_t)p * 16 + c]);

    const float4* w4 = (const float4*)g_w;
    float4 a = w4[c];
    float4 d = w4[16 + c];
    float rs = v.x * a.x + v.y * a.y + v.z * a.z + v.w * a.w;
    float rd = v.x * d.x + v.y * d.y + v.z * d.z + v.w * d.w;
    #pragma unroll
    for (int o = 8; o >= 1; o >>= 1) {
        rs += __shfl_down_sync(0xffffffffu, rs, o, 16);
        rd += __shfl_down_sync(0xffffffffu, rd, o, 16);
    }
    if (c == 0) {
        g_ea[n]  = __expf(rs);
        g_ed[n]  = __expf(rd);
        g_cnt[n] = 0;
    }
}

// ---------------------------------------------------------------------------
// K2: two edges per thread; append {poi_row(neighbor), f32 weight} records
// for both directions. Weight = product of pre-exponentiated factors (one
// FMUL after the gathers; no MUFU in the chain). No float atomics — K3
// rebuilds the softmax denominator from the record weights. Max-subtraction
// omitted (scores ~ N(0,2), softmax is shift-invariant; f32 exp is safe).
// ---------------------------------------------------------------------------
__global__ void k2_build(const int* __restrict__ esrc,
                         const int* __restrict__ edst,
                         const int* __restrict__ edist,
                         const int* __restrict__ sess) {
    int i = blockIdx.x * blockDim.x + threadIdx.x;
    if (i >= NEDGES / 2) return;
    int2 ss = __ldg(&((const int2*)esrc)[i]);
    int2 tt = __ldg(&((const int2*)edst)[i]);
    int2 kk = __ldg(&((const int2*)edist)[i]);

    float ef0 = __ldg(&g_ea[tt.x]) * __ldg(&g_expb[kk.x]);
    float ef1 = __ldg(&g_ea[tt.y]) * __ldg(&g_expb[kk.y]);
    float eb0 = __ldg(&g_ed[ss.x]);
    float eb1 = __ldg(&g_ed[ss.y]);

    int ps0 = __ldg(&sess[ss.x]);   // poi row of message source s
    int pt0 = __ldg(&sess[tt.x]);   // poi row of message source t
    int ps1 = __ldg(&sess[ss.y]);
    int pt1 = __ldg(&sess[tt.y]);

    int p0 = atomicAdd(&g_cnt[tt.x], 1);
    int p1 = atomicAdd(&g_cnt[ss.x], 1);
    int p2 = atomicAdd(&g_cnt[tt.y], 1);
    int p3 = atomicAdd(&g_cnt[ss.y], 1);
    if (p0 < SLOTS) g_adj[tt.x * SLOTS + p0] = make_int2(ps0, __float_as_int(ef0));
    if (p1 < SLOTS) g_adj[ss.x * SLOTS + p1] = make_int2(pt0, __float_as_int(eb0));
    if (p2 < SLOTS) g_adj[tt.y * SLOTS + p2] = make_int2(ps1, __float_as_int(ef1));
    if (p3 < SLOTS) g_adj[ss.y * SLOTS + p3] = make_int2(pt1, __float_as_int(eb1));
}

// ---------------------------------------------------------------------------
// K3: warp-per-node aggregation. Two half-warps; each half-warp batches FOUR
// records per iteration -> 8 independent L2 gathers in flight per warp.
// f32 gathers straight from the poi input (12.8MB, L2-resident); denominator
// summed from record weights; one coalesced normalized store. No atomics.
// ---------------------------------------------------------------------------
__global__ void k3_agg(const float* __restrict__ poi, float* __restrict__ out) {
    int w = (blockIdx.x * blockDim.x + threadIdx.x) >> 5;
    if (w >= NNODES) return;
    int lane = threadIdx.x & 31;
    int c = lane & 15;
    int h = lane >> 4;

    int deg = g_cnt[w];
    if (deg > SLOTS) deg = SLOTS;
    const int2* adj = g_adj + (size_t)w * SLOTS;
    const float4* x4 = (const float4*)poi;

    float4 acc = make_float4(0.f, 0.f, 0.f, 0.f);
    float  ssum = 0.f;

    int i = h;
    for (; i + 6 < deg; i += 8) {
        int2 r0 = __ldg(&adj[i]);
        int2 r1 = __ldg(&adj[i + 2]);
        int2 r2 = __ldg(&adj[i + 4]);
        int2 r3 = __ldg(&adj[i + 6]);
        float4 v0 = __ldg(&x4[(size_t)r0.x * 16 + c]);
        float4 v1 = __ldg(&x4[(size_t)r1.x * 16 + c]);
        float4 v2 = __ldg(&x4[(size_t)r2.x * 16 + c]);
        float4 v3 = __ldg(&x4[(size_t)r3.x * 16 + c]);
        float w0 = __int_as_float(r0.y);
        float w1 = __int_as_float(r1.y);
        float w2 = __int_as_float(r2.y);
        float w3 = __int_as_float(r3.y);
        ssum += (w0 + w1) + (w2 + w3);
        acc.x += w0 * v0.x + w1 * v1.x + w2 * v2.x + w3 * v3.x;
        acc.y += w0 * v0.y + w1 * v1.y + w2 * v2.y + w3 * v3.y;
        acc.z += w0 * v0.z + w1 * v1.z + w2 * v2.z + w3 * v3.z;
        acc.w += w0 * v0.w + w1 * v1.w + w2 * v2.w + w3 * v3.w;
    }
    for (; i < deg; i += 2) {
        int2 r = __ldg(&adj[i]);
        float wt = __int_as_float(r.y);
        float4 v = __ldg(&x4[(size_t)r.x * 16 + c]);
        ssum  += wt;
        acc.x += wt * v.x;
        acc.y += wt * v.y;
        acc.z += wt * v.z;
        acc.w += wt * v.w;
    }

    // combine the two half-warp partials (columns align: lane c and lane c+16)
    acc.x += __shfl_down_sync(0xffffffffu, acc.x, 16);
    acc.y += __shfl_down_sync(0xffffffffu, acc.y, 16);
    acc.z += __shfl_down_sync(0xffffffffu, acc.z, 16);
    acc.w += __shfl_down_sync(0xffffffffu, acc.w, 16);
    ssum  += __shfl_down_sync(0xffffffffu, ssum, 16);

    if (h == 0) {
        float inv = 1.f / (ssum + 1e-16f);
        acc.x *= inv; acc.y *= inv; acc.z *= inv; acc.w *= inv;
        ((float4*)out)[(size_t)w * 16 + c] = acc;
    }
}

// ---------------------------------------------------------------------------
extern "C" void kernel_launch(void* const* d_in, const int* in_sizes, int n_in,
                              void* d_out, int out_size) {
    const float* poi   = (const float*)d_in[0];  // [NPOI, D]
    const float* dis   = (const float*)d_in[1];  // [NDIST, D]
    const float* W     = (const float*)d_in[2];  // [D, D]
    const float* asw   = (const float*)d_in[3];  // [D]
    const float* adw   = (const float*)d_in[4];  // [D]
    const int*   sess  = (const int*)d_in[5];    // [NNODES]
    const int*   ei    = (const int*)d_in[6];    // [2, NEDGES]
    const int*   edist = (const int*)d_in[7];    // [NEDGES]
    float* out = (float*)d_out;                  // [NNODES, D]

    const int* esrc = ei;
    const int* edst = ei + NEDGES;

    k0_precompute<<<1, 256>>>(W, asw, adw, dis);
    k1_nodes<<<(NNODES * 16 + 255) / 256, 256>>>(poi, sess);
    k2_build<<<(NEDGES / 2 + 255) / 256, 256>>>(esrc, edst, edist, sess);
    k3_agg<<<(NNODES * 32 + 255) / 256, 256>>>(poi, out);
}